// round 16
// baseline (speedup 1.0000x reference)
#include <cuda_runtime.h>
#include <cuda_fp16.h>
#include <cstdint>

// ---------------- constants ----------------
#define GRID_CTAS 148
#define THREADS   544                   // 17 warps; 16 slots of 16 rows + overlap
#define TILE_M    256
#define NROWS     1048576
#define NTILES    4096                  // exact: every tile fully valid
#define TILE_F4   4096                  // TILE_M*16 float4s per tile

// smem byte offsets (from 1024-aligned dynamic base)
#define SM_B1CAT  0                     // 256 f32 layer-1 biases (b|c)
#define SM_B2S    1024                  // 128 f32 layer-2 biases (b|c)
#define SM_CNT    1536                  // 4 int counters (parity pairs)
#define SM_PERM   1600                  // 256 int: pos -> (row<<1)|isb
#define SM_B1     3072                  // W1cat fp16 [k=64][n=256] ld=264 -> 33792 B
#define SM_B2     36864                 // W2cat fp16 [k=256][n=64] ld=72  -> 36864 B
#define SM_A1     73728                 // obs tile fp16 [256][72] UNPERMUTED -> 36864 B
#define SM_XS     110592                // obs tile fp32 staging [256][64]   -> 65536 B
#define SMEM_BYTES (176128 + 1024)

#define LD1 264   // halfs per row of B1
#define LD2 72    // halfs per row of B2
#define LDA 72    // halfs per row of A1 (144 B)

// ---------------- ptx helpers ----------------
__device__ __forceinline__ uint32_t s2u(const void* p) {
    uint32_t a;
    asm("{ .reg .u64 t; cvta.to.shared.u64 t, %1; cvt.u32.u64 %0, t; }" : "=r"(a) : "l"(p));
    return a;
}
__device__ __forceinline__ void ldsm_x4(uint32_t* r, uint32_t addr) {
    asm volatile("ldmatrix.sync.aligned.m8n8.x4.shared.b16 {%0,%1,%2,%3}, [%4];"
                 : "=r"(r[0]), "=r"(r[1]), "=r"(r[2]), "=r"(r[3]) : "r"(addr));
}
__device__ __forceinline__ void ldsm_x4t(uint32_t* r, uint32_t addr) {
    asm volatile("ldmatrix.sync.aligned.m8n8.x4.trans.shared.b16 {%0,%1,%2,%3}, [%4];"
                 : "=r"(r[0]), "=r"(r[1]), "=r"(r[2]), "=r"(r[3]) : "r"(addr));
}
// NOTE: intentionally NOT volatile — pure register op; lets the scheduler
// interleave mma chains with loads and across groups.
__device__ __forceinline__ void mma16816(float* d, const uint32_t* a, uint32_t b0, uint32_t b1) {
    asm("mma.sync.aligned.m16n8k16.row.col.f32.f16.f16.f32 "
        "{%0,%1,%2,%3}, {%4,%5,%6,%7}, {%8,%9}, {%0,%1,%2,%3};"
        : "+f"(d[0]), "+f"(d[1]), "+f"(d[2]), "+f"(d[3])
        : "r"(a[0]), "r"(a[1]), "r"(a[2]), "r"(a[3]), "r"(b0), "r"(b1));
}
__device__ __forceinline__ void cp16(uint32_t dst, const void* src) {
    asm volatile("cp.async.cg.shared.global [%0], [%1], 16;" :: "r"(dst), "l"(src));
}
#define CP_COMMIT() asm volatile("cp.async.commit_group;" ::: "memory")
#define CP_WAIT0()  asm volatile("cp.async.wait_group 0;" ::: "memory")

__device__ __forceinline__ uint32_t packh2(float x, float y) {
    __half2 h = __floats2half2_rn(x, y);
    return *reinterpret_cast<uint32_t*>(&h);
}

// ---------------- kernel ----------------
extern "C" __global__ void __launch_bounds__(THREADS, 1)
STAR_moe_mlp_kernel(
    const float* __restrict__ obs,
    const float* __restrict__ W1b, const float* __restrict__ b1b,
    const float* __restrict__ W2b, const float* __restrict__ b2b,
    const float* __restrict__ W1c, const float* __restrict__ b1c,
    const float* __restrict__ W2c, const float* __restrict__ b2c,
    const float* __restrict__ W1p, const float* __restrict__ b1p,
    const float* __restrict__ W2p, const float* __restrict__ b2p,
    float* __restrict__ out)
{
    extern __shared__ char smem_raw[];
    uint32_t sb0 = s2u(smem_raw);
    uint32_t sb  = (sb0 + 1023u) & ~1023u;
    char* smb = smem_raw + (sb - sb0);

    const int tid = threadIdx.x;
    const int wid = tid >> 5, l = tid & 31;

    int*   perm  = reinterpret_cast<int*>(smb + SM_PERM);
    int*   cnts  = reinterpret_cast<int*>(smb + SM_CNT);
    float* b1cat = reinterpret_cast<float*>(smb + SM_B1CAT);
    float* b2s   = reinterpret_cast<float*>(smb + SM_B2S);

    // ---- one-time setup: fused weights (fp16) + biases into SMEM ----
    for (int idx = tid; idx < 64 * 256; idx += THREADS) {       // B1: [k=64][n=256] (b|c)
        int k = idx >> 8, n = idx & 255;
        float w = (n < 128) ? W1b[k * 128 + n] * W1p[k * 128 + n]
                            : W1c[k * 128 + (n - 128)] * W1p[k * 128 + (n - 128)];
        *reinterpret_cast<__half*>(smb + SM_B1 + (uint32_t)(k * LD1 + n) * 2) = __float2half_rn(w);
    }
    for (int idx = tid; idx < 256 * 64; idx += THREADS) {       // B2: [k=256][n=64] (b|c in k)
        int k = idx >> 6, n = idx & 63;
        float w = (k < 128) ? W2b[k * 64 + n] * W2p[k * 64 + n]
                            : W2c[(k - 128) * 64 + n] * W2p[(k - 128) * 64 + n];
        *reinterpret_cast<__half*>(smb + SM_B2 + (uint32_t)(k * LD2 + n) * 2) = __float2half_rn(w);
    }
    for (int i = tid; i < 256; i += THREADS)
        b1cat[i] = (i < 128) ? b1b[i] + b1p[i] : b1c[i - 128] + b1p[i - 128];
    for (int i = tid; i < 128; i += THREADS)
        b2s[i] = (i < 64) ? b2b[i] + b2p[i] : b2c[i - 64] + b2p[i - 64];
    if (tid < 4) cnts[tid] = 0;

    // ---- prologue: stage first tile ----
    {
        const float4* g = reinterpret_cast<const float4*>(obs + (size_t)blockIdx.x * (TILE_M * 64));
        #pragma unroll
        for (int i = 0; i < 8; i++) {
            int f = i * THREADS + tid;
            if (f < TILE_F4) cp16(sb + SM_XS + (uint32_t)f * 16, g + f);
        }
    }
    CP_COMMIT();

    for (int it = 0;; it++) {
        int tile = blockIdx.x + it * GRID_CTAS;
        if (tile >= NTILES) break;
        const int par = it & 1;
        int* cb = cnts + par * 2;

        CP_WAIT0();
        __syncthreads();                       // XS ready; prev compute (A1/perm reads) done

        // ---- single preprocessing phase: counter-reset + perm atomics + convert ----
        if (tid == 0) { cnts[(par ^ 1) * 2] = 0; cnts[(par ^ 1) * 2 + 1] = 0; }
        {
            const float4* xs4 = reinterpret_cast<const float4*>(smb + SM_XS);
            #pragma unroll
            for (int i = 0; i < 8; i++) {
                int f = i * THREADS + tid;
                if (f < TILE_F4) {
                    int row = f >> 4, c4 = f & 15;
                    float4 v = xs4[f];
                    if (c4 == 0) {                          // cols 2,3 are routing flags
                        bool isb = (v.z == 1.0f && v.w == 0.0f);
                        int pos = isb ? atomicAdd(&cb[0], 1)
                                      : (TILE_M - 1) - atomicAdd(&cb[1], 1);
                        perm[pos] = (row << 1) | (isb ? 1 : 0);
                    }
                    uint2 pp;
                    pp.x = packh2(v.x, v.y);
                    pp.y = packh2(v.z, v.w);
                    *reinterpret_cast<uint2*>(smb + SM_A1 + (uint32_t)(row * (LDA * 2) + c4 * 8)) = pp;
                }
            }
        }
        __syncthreads();

        // ---- prefetch next tile (XS free; overlaps compute) ----
        int nt = tile + GRID_CTAS;
        if (nt < NTILES) {
            const float4* g = reinterpret_cast<const float4*>(obs + (size_t)nt * (TILE_M * 64));
            #pragma unroll
            for (int i = 0; i < 8; i++) {
                int f = i * THREADS + tid;
                if (f < TILE_F4) cp16(sb + SM_XS + (uint32_t)f * 16, g + f);
            }
        }
        CP_COMMIT();

        // ---- slot assignment: one 16-row single-expert slot per warp ----
        int cnt_b = cb[0], cnt_c = cb[1];
        int cstart = TILE_M - cnt_c;
        int sb_slots = (cnt_b + 15) >> 4;
        int slot, e;
        bool active;
        if (wid < sb_slots) { slot = wid; e = 1; active = true; }
        else { slot = (cstart >> 4) + (wid - sb_slots); e = 0; active = (slot <= 15); }

        if (active) {
            const int ebase = e ? 0 : 128;   // b at hidden [0,128), c at [128,256)

            // ---- A fragments via ldmatrix ROW-GATHER through perm ----
            int pv = perm[slot * 16 + (l & 15)];
            int grow = pv >> 1;
            uint32_t abase = sb + SM_A1 + (uint32_t)grow * (LDA * 2) + (uint32_t)((l >> 4) * 16);
            uint32_t a1f[4][4];
            #pragma unroll
            for (int kb = 0; kb < 4; kb++)
                ldsm_x4(a1f[kb], abase + kb * 32);

            float acc2[8][4];
            #pragma unroll
            for (int nbt = 0; nbt < 8; nbt++)
                #pragma unroll
                for (int q = 0; q < 4; q++) acc2[nbt][q] = 0.f;

            // ---- interleaved: per n16 hidden group:
            //      ALL loads first (B1 + B2), then L1 mma -> relu -> L2 mma ----
            #pragma unroll
            for (int c = 0; c < 2; c++) {
                int hbase = ebase + c * 64;
                #pragma unroll
                for (int p = 0; p < 4; p++) {
                    // issue all 8 smem loads for this group up front
                    uint32_t b1f[4][4];
                    #pragma unroll
                    for (int kb = 0; kb < 4; kb++)
                        ldsm_x4t(b1f[kb], sb + SM_B1 + (uint32_t)((kb * 16 + (l & 15)) * LD1
                                                                  + hbase + p * 16 + (l >> 4) * 8) * 2);
                    uint32_t b2f[4][4];
                    #pragma unroll
                    for (int p2 = 0; p2 < 4; p2++)
                        ldsm_x4t(b2f[p2], sb + SM_B2 + (uint32_t)((hbase + p * 16 + (l & 15)) * LD2
                                                                  + p2 * 16 + (l >> 4) * 8) * 2);

                    // L1 mma chain (two independent accumulators)
                    float acc1[2][4];
                    #pragma unroll
                    for (int j = 0; j < 2; j++)
                        #pragma unroll
                        for (int q = 0; q < 4; q++) acc1[j][q] = 0.f;
                    #pragma unroll
                    for (int kb = 0; kb < 4; kb++) {
                        mma16816(acc1[0], a1f[kb], b1f[kb][0], b1f[kb][1]);
                        mma16816(acc1[1], a1f[kb], b1f[kb][2], b1f[kb][3]);
                    }

                    // bias + relu -> fp16 L2-A fragment for this k16 group
                    uint32_t a2[4];
                    #pragma unroll
                    for (int j = 0; j < 2; j++) {
                        int colb = hbase + p * 16 + j * 8 + 2 * (l & 3);
                        float2 bi = *reinterpret_cast<const float2*>(b1cat + colb);
                        float v0 = fmaxf(acc1[j][0] + bi.x, 0.f);
                        float v1 = fmaxf(acc1[j][1] + bi.y, 0.f);
                        float v2 = fmaxf(acc1[j][2] + bi.x, 0.f);
                        float v3 = fmaxf(acc1[j][3] + bi.y, 0.f);
                        a2[j * 2 + 0] = packh2(v0, v1);
                        a2[j * 2 + 1] = packh2(v2, v3);
                    }

                    // L2 partial accumulation (fp32 accum)
                    #pragma unroll
                    for (int p2 = 0; p2 < 4; p2++) {
                        mma16816(acc2[2 * p2],     a2, b2f[p2][0], b2f[p2][1]);
                        mma16816(acc2[2 * p2 + 1], a2, b2f[p2][2], b2f[p2][3]);
                    }
                }
            }

            // ---- store: routed bias, scatter by perm, gate overlap rows ----
            const float* bb = b2s + (e ? 0 : 64);
            int p0 = slot * 16 + (l >> 2), p1 = p0 + 8;
            int v0 = perm[p0], v1 = perm[p1];
            bool s0 = ((v0 & 1) == e);
            bool s1 = ((v1 & 1) == e);
            size_t base = (size_t)tile * TILE_M;
            float* o0 = out + (base + (size_t)(v0 >> 1)) * 64;
            float* o1 = out + (base + (size_t)(v1 >> 1)) * 64;
            #pragma unroll
            for (int nbt = 0; nbt < 8; nbt++) {
                int cb2 = nbt * 8 + (l & 3) * 2;
                if (s0) {
                    float2 o; o.x = acc2[nbt][0] + bb[cb2]; o.y = acc2[nbt][1] + bb[cb2 + 1];
                    *reinterpret_cast<float2*>(o0 + cb2) = o;
                }
                if (s1) {
                    float2 o; o.x = acc2[nbt][2] + bb[cb2]; o.y = acc2[nbt][3] + bb[cb2 + 1];
                    *reinterpret_cast<float2*>(o1 + cb2) = o;
                }
            }
        }
    }
}

// ---------------- launch ----------------
extern "C" void kernel_launch(void* const* d_in, const int* in_sizes, int n_in,
                              void* d_out, int out_size) {
    (void)in_sizes; (void)n_in; (void)out_size;
    cudaFuncSetAttribute(STAR_moe_mlp_kernel,
                         cudaFuncAttributeMaxDynamicSharedMemorySize, SMEM_BYTES);
    STAR_moe_mlp_kernel<<<GRID_CTAS, THREADS, SMEM_BYTES>>>(
        (const float*)d_in[0],
        (const float*)d_in[1],  (const float*)d_in[2],
        (const float*)d_in[3],  (const float*)d_in[4],
        (const float*)d_in[5],  (const float*)d_in[6],
        (const float*)d_in[7],  (const float*)d_in[8],
        (const float*)d_in[9],  (const float*)d_in[10],
        (const float*)d_in[11], (const float*)d_in[12],
        (float*)d_out);
}